// round 12
// baseline (speedup 1.0000x reference)
#include <cuda_runtime.h>
#include <cuda_fp16.h>
#include <cstdint>
#include <cstddef>

#define N_NODES   50000
#define N_EDGES   800000
#define C_DIM     256
#define R_REL     4
#define NBUCKETS  (R_REL * N_NODES)
#define SCAN_BS   1024
#define NSCANBLK  ((NBUCKETS + SCAN_BS - 1) / SCAN_BS)

// -------------------- scratch --------------------
__device__ int g_deg[NBUCKETS];
__device__ int g_off[NBUCKETS];     // after bucket_kernel: off_final = off + deg
__device__ int g_eidx[N_EDGES];
__device__ int g_bsum[SCAN_BS];
__device__ int g_bsumx[SCAN_BS];
// fp16 weights [5][256][256] in [k][n] layout (root, rel0..3)
__device__ __half g_W[5 * C_DIM * C_DIM];
// fp16 A operand [5][N][256]: m=0 -> X(fp16), m=1..4 -> per-relation means
__device__ __half g_A[(size_t)5 * N_NODES * C_DIM];

__device__ __forceinline__ bool edge_ok(int s, int d, int r) {
    return ((unsigned)s < (unsigned)N_NODES) &&
           ((unsigned)d < (unsigned)N_NODES) &&
           ((unsigned)r < (unsigned)R_REL);
}

// ---------------------------------------------------------------------------
// CSR build (edges are INT32)
// ---------------------------------------------------------------------------
__global__ void zero_counts_kernel() {
    int i = blockIdx.x * blockDim.x + threadIdx.x;
    if (i < NBUCKETS) g_deg[i] = 0;
}

__global__ void hist_kernel(const int* __restrict__ edge_index,
                            const int* __restrict__ edge_type) {
    int e = blockIdx.x * blockDim.x + threadIdx.x;
    if (e >= N_EDGES) return;
    int s = edge_index[e];
    int d = edge_index[N_EDGES + e];
    int r = edge_type[e];
    if (!edge_ok(s, d, r)) return;
    atomicAdd(&g_deg[r * N_NODES + d], 1);
}

__global__ void scan_blocks_kernel() {
    __shared__ int sh[SCAN_BS];
    const int tid = threadIdx.x;
    const int gid = blockIdx.x * SCAN_BS + tid;
    int v = (gid < NBUCKETS) ? g_deg[gid] : 0;
    sh[tid] = v;
    __syncthreads();
    for (int o = 1; o < SCAN_BS; o <<= 1) {
        int t = (tid >= o) ? sh[tid - o] : 0;
        __syncthreads();
        sh[tid] += t;
        __syncthreads();
    }
    int incl = sh[tid];
    if (gid < NBUCKETS) g_off[gid] = incl - v;
    if (tid == SCAN_BS - 1) g_bsum[blockIdx.x] = incl;
}

__global__ void scan_top_kernel() {
    __shared__ int sh[256];
    const int tid = threadIdx.x;
    int v = (tid < NSCANBLK) ? g_bsum[tid] : 0;
    sh[tid] = v;
    __syncthreads();
    for (int o = 1; o < 256; o <<= 1) {
        int t = (tid >= o) ? sh[tid - o] : 0;
        __syncthreads();
        sh[tid] += t;
        __syncthreads();
    }
    g_bsumx[tid] = sh[tid] - v;
}

__global__ void scan_add_kernel() {
    int i = blockIdx.x * blockDim.x + threadIdx.x;
    if (i < NBUCKETS) g_off[i] += g_bsumx[i >> 10];
}

// bucket: post-increment g_off itself (no cursor array)
__global__ void bucket_kernel(const int* __restrict__ edge_index,
                              const int* __restrict__ edge_type) {
    int e = blockIdx.x * blockDim.x + threadIdx.x;
    if (e >= N_EDGES) return;
    int s = edge_index[e];
    int d = edge_index[N_EDGES + e];
    int r = edge_type[e];
    if (!edge_ok(s, d, r)) return;
    int b = r * N_NODES + d;
    int pos = atomicAdd(&g_off[b], 1);
    if ((unsigned)pos < (unsigned)N_EDGES)
        g_eidx[pos] = s;
}

// ---------------------------------------------------------------------------
// Fused conversion: W -> fp16 [m][k][n]; X -> g_A slot 0
// ---------------------------------------------------------------------------
#define W_G4 (5 * C_DIM * C_DIM / 4)          // 81920 float4-granules of W
#define X_G4 (N_NODES * C_DIM / 4)            // 3,200,000 granules of X
__global__ void conv_kernel(const float* __restrict__ relW,
                            const float* __restrict__ rootW,
                            const float* __restrict__ X) {
    int gid = blockIdx.x * blockDim.x + threadIdx.x;
    if (gid < W_G4) {
        const int i = gid * 4;        // element index into [5][64k]
        const int m = i >> 16;
        const int o = i & 65535;
        const float4 v = (m == 0)
            ? *reinterpret_cast<const float4*>(rootW + o)
            : *reinterpret_cast<const float4*>(relW + (size_t)(m - 1) * 65536 + o);
        __half h[4];
        h[0] = __float2half(v.x); h[1] = __float2half(v.y);
        h[2] = __float2half(v.z); h[3] = __float2half(v.w);
        *reinterpret_cast<uint2*>(g_W + i) = *reinterpret_cast<uint2*>(h);
    } else if (gid < W_G4 + X_G4) {
        const size_t i = (size_t)(gid - W_G4);
        const float4 v = reinterpret_cast<const float4*>(X)[i];
        __half h[4];
        h[0] = __float2half(v.x); h[1] = __float2half(v.y);
        h[2] = __float2half(v.z); h[3] = __float2half(v.w);
        *reinterpret_cast<uint2*>(g_A + 4 * i) = *reinterpret_cast<uint2*>(h);
    }
}

// ---------------------------------------------------------------------------
// Gather-mean per bucket over fp16 X -> g_A[1+r]  (edge loop unrolled x2)
// ---------------------------------------------------------------------------
__device__ __forceinline__ void acc_row(float* s, int src, int lane) {
    const uint4 raw = *reinterpret_cast<const uint4*>(
        g_A + (size_t)src * C_DIM + lane * 8);
    const __half2* hp = reinterpret_cast<const __half2*>(&raw);
    #pragma unroll
    for (int q = 0; q < 4; ++q) {
        const float2 f = __half22float2(hp[q]);
        s[2 * q]     += f.x;
        s[2 * q + 1] += f.y;
    }
}

__global__ void agg_kernel() {
    const int wid  = (blockIdx.x * blockDim.x + threadIdx.x) >> 5;
    const int lane = threadIdx.x & 31;
    if (wid >= NBUCKETS) return;

    const int deg   = g_deg[wid];
    const int start = g_off[wid] - deg;    // off was post-incremented by bucket

    float s[8] = {0.f, 0.f, 0.f, 0.f, 0.f, 0.f, 0.f, 0.f};
    float s2[8] = {0.f, 0.f, 0.f, 0.f, 0.f, 0.f, 0.f, 0.f};
    int e = 0;
    for (; e + 1 < deg; e += 2) {
        const int src0 = g_eidx[start + e];
        const int src1 = g_eidx[start + e + 1];
        acc_row(s,  src0, lane);
        acc_row(s2, src1, lane);
    }
    if (e < deg) acc_row(s, g_eidx[start + e], lane);
    #pragma unroll
    for (int q = 0; q < 8; ++q) s[q] += s2[q];

    const float inv = (deg > 0) ? (1.0f / (float)deg) : 0.0f;

    __half h[8];
    #pragma unroll
    for (int q = 0; q < 8; ++q) h[q] = __float2half(s[q] * inv);

    const size_t o = ((size_t)N_NODES * C_DIM) + (size_t)wid * C_DIM + lane * 8;
    *reinterpret_cast<uint4*>(g_A + o) = *reinterpret_cast<uint4*>(h);
}

// ---------------------------------------------------------------------------
// Dense GEMM (K=1280 concat, single-pass fp16) + gate epilogue.
// Tile M=128 x N=256, 512 threads = 16 warps (8m x 2n). 2-stage, KCH=128.
// px (X . attW_x) computed in-kernel before the main loop.
// ---------------------------------------------------------------------------
#define MB      128
#define KCH     128
#define NCHUNK  10
#define SAW     136     // A smem row stride (half): 272B, conflict-free
#define SWW     264     // W smem row stride (half)
#define A_STAGE (MB * SAW)              // 17408 half
#define W_STAGE (KCH * SWW)             // 33792 half
#define STAGE_H (A_STAGE + W_STAGE)     // 51200 half
#define SMEM_BYTES (2 * STAGE_H * 2)    // 204,800 B

__device__ __forceinline__ void cp16(void* dst_smem, const void* src) {
    unsigned int d = (unsigned int)__cvta_generic_to_shared(dst_smem);
    asm volatile("cp.async.cg.shared.global [%0], [%1], 16;" :: "r"(d), "l"(src));
}
__device__ __forceinline__ void ldsm4(const void* p, unsigned& r0, unsigned& r1,
                                      unsigned& r2, unsigned& r3) {
    unsigned a = (unsigned)__cvta_generic_to_shared(p);
    asm volatile("ldmatrix.sync.aligned.m8n8.x4.shared.b16 {%0,%1,%2,%3}, [%4];"
                 : "=r"(r0), "=r"(r1), "=r"(r2), "=r"(r3) : "r"(a));
}
__device__ __forceinline__ void ldsm4t(const void* p, unsigned& r0, unsigned& r1,
                                       unsigned& r2, unsigned& r3) {
    unsigned a = (unsigned)__cvta_generic_to_shared(p);
    asm volatile("ldmatrix.sync.aligned.m8n8.x4.trans.shared.b16 {%0,%1,%2,%3}, [%4];"
                 : "=r"(r0), "=r"(r1), "=r"(r2), "=r"(r3) : "r"(a));
}
__device__ __forceinline__ void mma16816(float* c, unsigned a0, unsigned a1,
                                         unsigned a2, unsigned a3,
                                         unsigned b0, unsigned b1) {
    asm volatile(
        "mma.sync.aligned.m16n8k16.row.col.f32.f16.f16.f32 "
        "{%0,%1,%2,%3}, {%4,%5,%6,%7}, {%8,%9}, {%0,%1,%2,%3};"
        : "+f"(c[0]), "+f"(c[1]), "+f"(c[2]), "+f"(c[3])
        : "r"(a0), "r"(a1), "r"(a2), "r"(a3), "r"(b0), "r"(b1));
}

__global__ void __launch_bounds__(512, 1) gemm_gate(
    const float* __restrict__ X,
    const float* __restrict__ bias,
    const float* __restrict__ attW,
    const float* __restrict__ attB,
    float* __restrict__ out)
{
    extern __shared__ char smem_raw[];
    __half* sm = (__half*)smem_raw;
    float* pa = (float*)smem_raw;       // epilogue overlay
    __shared__ float spx[MB];           // px per tile row (static, survives overlay)

    const int t    = threadIdx.x;
    const int lane = t & 31;
    const int warp = t >> 5;
    const int wm   = warp & 7;      // 8 m-warps x 16 rows
    const int wn   = warp >> 3;     // 2 n-warps x 128 cols
    const int node0 = blockIdx.x * MB;

    float acc[16][4];
    #pragma unroll
    for (int i = 0; i < 16; ++i)
        #pragma unroll
        for (int j = 0; j < 4; ++j) acc[i][j] = 0.f;

    auto load_chunk = [&](int c, int stage) {
        const int m  = c >> 1;
        const int k0 = (c & 1) * KCH;
        __half* st = sm + stage * STAGE_H;
        // A: 128 rows x 16 segs = 2048 granules -> 4 per thread
        #pragma unroll
        for (int i = 0; i < 4; ++i) {
            const int p = t + 512 * i;          // 0..2047
            const int row = p >> 4, seg = p & 15;
            const int node = min(node0 + row, N_NODES - 1);
            const size_t g = ((size_t)m * N_NODES + node) * C_DIM + k0 + seg * 8;
            cp16(st + row * SAW + seg * 8, g_A + g);
        }
        // W: 128 rows x 32 segs = 4096 granules -> 8 per thread
        #pragma unroll
        for (int i = 0; i < 8; ++i) {
            const int p = t + 512 * i;          // 0..4095
            const int row = p >> 5, seg = p & 31;
            const size_t g = ((size_t)m * C_DIM + k0 + row) * C_DIM + seg * 8;
            cp16(st + A_STAGE + row * SWW + seg * 8, g_W + g);
        }
        asm volatile("cp.async.commit_group;");
    };

    load_chunk(0, 0);

    // ---- px = X16[node] . attW[C:2C], 4 threads per row (overlaps load 0) ----
    {
        const int prow = t >> 2;            // 0..127
        const int pq   = t & 3;
        const int pnode = min(node0 + prow, N_NODES - 1);
        const __half* xrow = g_A + (size_t)pnode * C_DIM + pq * 64;
        float pxv = 0.f;
        #pragma unroll
        for (int j = 0; j < 8; ++j) {
            const uint4 raw = *reinterpret_cast<const uint4*>(xrow + j * 8);
            const __half2* hp = reinterpret_cast<const __half2*>(&raw);
            #pragma unroll
            for (int q = 0; q < 4; ++q) {
                const float2 f = __half22float2(hp[q]);
                const int col = C_DIM + pq * 64 + j * 8 + 2 * q;
                pxv += f.x * attW[col] + f.y * attW[col + 1];
            }
        }
        pxv += __shfl_xor_sync(0xffffffffu, pxv, 1);
        pxv += __shfl_xor_sync(0xffffffffu, pxv, 2);
        if (pq == 0) spx[prow] = pxv;
    }

    for (int c = 0; c < NCHUNK; ++c) {
        asm volatile("cp.async.wait_group 0;");   // load c complete
        __syncthreads();   // all warps done reading stage (c+1)&1 (iter c-1)

        if (c + 1 < NCHUNK) load_chunk(c + 1, (c + 1) & 1);

        const __half* st = sm + (c & 1) * STAGE_H;
        const __half* Wb = st + A_STAGE;

        #pragma unroll
        for (int s = 0; s < 8; ++s) {
            const __half* ap =
                st + (wm * 16 + (lane & 15)) * SAW + s * 16 + (lane >> 4) * 8;
            unsigned a0, a1, a2, a3;
            ldsm4(ap, a0, a1, a2, a3);

            const int krow = s * 16 + (lane & 15);
            #pragma unroll
            for (int nt2 = 0; nt2 < 8; ++nt2) {
                const int ncol = wn * 128 + nt2 * 16 + (lane >> 4) * 8;
                unsigned b0, b1, b2, b3;
                ldsm4t(Wb + krow * SWW + ncol, b0, b1, b2, b3);
                mma16816(acc[2 * nt2],     a0, a1, a2, a3, b0, b1);
                mma16816(acc[2 * nt2 + 1], a0, a1, a2, a3, b2, b3);
            }
        }
    }
    __syncthreads();   // all computes done before smem overlay

    // ---------------- epilogue (register-resident; px in spx) ----------
    const int r0   = lane >> 2;
    const int cq   = 2 * (lane & 3);
    const int row0 = wm * 16 + r0;
    const int n0g  = node0 + row0;
    const int n1g  = n0g + 8;
    const bool v0  = n0g < N_NODES;
    const bool v1  = n1g < N_NODES;

    float pz0 = 0.f, pz1 = 0.f;
    #pragma unroll
    for (int nt = 0; nt < 16; ++nt) {
        const int col = wn * 128 + (nt >> 1) * 16 + (nt & 1) * 8 + cq;
        const float b0 = bias[col], b1 = bias[col + 1];
        const float wu0 = attW[col], wu1 = attW[col + 1];
        pz0 += (acc[nt][0] + b0) * wu0 + (acc[nt][1] + b1) * wu1;
        pz1 += (acc[nt][2] + b0) * wu0 + (acc[nt][3] + b1) * wu1;
    }
    pz0 += __shfl_xor_sync(0xffffffffu, pz0, 1);
    pz0 += __shfl_xor_sync(0xffffffffu, pz0, 2);
    pz1 += __shfl_xor_sync(0xffffffffu, pz1, 1);
    pz1 += __shfl_xor_sync(0xffffffffu, pz1, 2);

    if ((lane & 3) == 0) {
        pa[row0 * 2 + wn]       = pz0;
        pa[(row0 + 8) * 2 + wn] = pz1;
    }
    __syncthreads();
    float* a_s = pa + 2 * MB;
    if (t < MB) {
        const float z = pa[t * 2] + pa[t * 2 + 1] + spx[t] + attB[0];
        a_s[t] = 1.0f / (1.0f + expf(-z));
    }
    __syncthreads();

    const float a0 = a_s[row0], a1 = a_s[row0 + 8];
    #pragma unroll
    for (int nt = 0; nt < 16; ++nt) {
        const int col = wn * 128 + (nt >> 1) * 16 + (nt & 1) * 8 + cq;
        const float b0 = bias[col], b1 = bias[col + 1];
        if (v0) {
            const float2 x2 = *reinterpret_cast<const float2*>(X + (size_t)n0g * C_DIM + col);
            float2 h;
            h.x = tanhf(acc[nt][0] + b0) * a0 + x2.x * (1.0f - a0);
            h.y = tanhf(acc[nt][1] + b1) * a0 + x2.y * (1.0f - a0);
            *reinterpret_cast<float2*>(out + (size_t)n0g * C_DIM + col) = h;
        }
        if (v1) {
            const float2 x2 = *reinterpret_cast<const float2*>(X + (size_t)n1g * C_DIM + col);
            float2 h;
            h.x = tanhf(acc[nt][2] + b0) * a1 + x2.x * (1.0f - a1);
            h.y = tanhf(acc[nt][3] + b1) * a1 + x2.y * (1.0f - a1);
            *reinterpret_cast<float2*>(out + (size_t)n1g * C_DIM + col) = h;
        }
    }
}

// ---------------------------------------------------------------------------
// Launch
// ---------------------------------------------------------------------------
extern "C" void kernel_launch(void* const* d_in, const int* in_sizes, int n_in,
                              void* d_out, int out_size) {
    const float* X     = (const float*)d_in[0];
    const int*   ei    = (const int*)d_in[1];     // int32
    const int*   et    = (const int*)d_in[2];     // int32
    const float* relW  = (const float*)d_in[3];
    const float* rootW = (const float*)d_in[4];
    const float* bias  = (const float*)d_in[5];
    const float* attW  = (const float*)d_in[6];
    const float* attB  = (const float*)d_in[7];
    float*       out   = (float*)d_out;
    (void)in_sizes; (void)n_in; (void)out_size;

    cudaFuncSetAttribute(gemm_gate,
                         cudaFuncAttributeMaxDynamicSharedMemorySize, SMEM_BYTES);

    zero_counts_kernel<<<(NBUCKETS + 255) / 256, 256>>>();
    hist_kernel<<<(N_EDGES + 255) / 256, 256>>>(ei, et);
    conv_kernel<<<(W_G4 + X_G4 + 255) / 256, 256>>>(relW, rootW, X);
    scan_blocks_kernel<<<NSCANBLK, SCAN_BS>>>();
    scan_top_kernel<<<1, 256>>>();
    scan_add_kernel<<<(NBUCKETS + 255) / 256, 256>>>();
    bucket_kernel<<<(N_EDGES + 255) / 256, 256>>>(ei, et);
    agg_kernel<<<(NBUCKETS * 32 + 255) / 256, 256>>>();
    gemm_gate<<<(N_NODES + MB - 1) / MB, 512, SMEM_BYTES>>>(X, bias, attW, attB, out);
}

// round 13
// speedup vs baseline: 1.0049x; 1.0049x over previous
#include <cuda_runtime.h>
#include <cuda_fp16.h>
#include <cstdint>
#include <cstddef>

#define N_NODES   50000
#define N_EDGES   800000
#define C_DIM     256
#define R_REL     4
#define NBUCKETS  (R_REL * N_NODES)
#define SCAN_BS   1024
#define NSCANBLK  ((NBUCKETS + SCAN_BS - 1) / SCAN_BS)

// -------------------- scratch --------------------
__device__ int g_deg[NBUCKETS];
__device__ int g_off[NBUCKETS];     // after bucket_kernel: off_final = off + deg
__device__ int g_eidx[N_EDGES];
__device__ int g_bsum[SCAN_BS];
__device__ int g_bsumx[SCAN_BS];
// fp16 weights [5][256][256] in [k][n] layout (root, rel0..3)
__device__ __half g_W[5 * C_DIM * C_DIM];
// fp16 A operand [5][N][256]: m=0 -> X(fp16), m=1..4 -> per-relation means
__device__ __half g_A[(size_t)5 * N_NODES * C_DIM];

__device__ __forceinline__ bool edge_ok(int s, int d, int r) {
    return ((unsigned)s < (unsigned)N_NODES) &&
           ((unsigned)d < (unsigned)N_NODES) &&
           ((unsigned)r < (unsigned)R_REL);
}

// ---------------------------------------------------------------------------
// CSR build (edges are INT32)
// ---------------------------------------------------------------------------
__global__ void zero_counts_kernel() {
    int i = blockIdx.x * blockDim.x + threadIdx.x;
    if (i < NBUCKETS) g_deg[i] = 0;
}

__global__ void hist_kernel(const int* __restrict__ edge_index,
                            const int* __restrict__ edge_type) {
    int e = blockIdx.x * blockDim.x + threadIdx.x;
    if (e >= N_EDGES) return;
    int s = edge_index[e];
    int d = edge_index[N_EDGES + e];
    int r = edge_type[e];
    if (!edge_ok(s, d, r)) return;
    atomicAdd(&g_deg[r * N_NODES + d], 1);
}

__global__ void scan_blocks_kernel() {
    __shared__ int sh[SCAN_BS];
    const int tid = threadIdx.x;
    const int gid = blockIdx.x * SCAN_BS + tid;
    int v = (gid < NBUCKETS) ? g_deg[gid] : 0;
    sh[tid] = v;
    __syncthreads();
    for (int o = 1; o < SCAN_BS; o <<= 1) {
        int t = (tid >= o) ? sh[tid - o] : 0;
        __syncthreads();
        sh[tid] += t;
        __syncthreads();
    }
    int incl = sh[tid];
    if (gid < NBUCKETS) g_off[gid] = incl - v;
    if (tid == SCAN_BS - 1) g_bsum[blockIdx.x] = incl;
}

__global__ void scan_top_kernel() {
    __shared__ int sh[256];
    const int tid = threadIdx.x;
    int v = (tid < NSCANBLK) ? g_bsum[tid] : 0;
    sh[tid] = v;
    __syncthreads();
    for (int o = 1; o < 256; o <<= 1) {
        int t = (tid >= o) ? sh[tid - o] : 0;
        __syncthreads();
        sh[tid] += t;
        __syncthreads();
    }
    g_bsumx[tid] = sh[tid] - v;
}

__global__ void scan_add_kernel() {
    int i = blockIdx.x * blockDim.x + threadIdx.x;
    if (i < NBUCKETS) g_off[i] += g_bsumx[i >> 10];
}

// bucket: post-increment g_off itself (no cursor array)
__global__ void bucket_kernel(const int* __restrict__ edge_index,
                              const int* __restrict__ edge_type) {
    int e = blockIdx.x * blockDim.x + threadIdx.x;
    if (e >= N_EDGES) return;
    int s = edge_index[e];
    int d = edge_index[N_EDGES + e];
    int r = edge_type[e];
    if (!edge_ok(s, d, r)) return;
    int b = r * N_NODES + d;
    int pos = atomicAdd(&g_off[b], 1);
    if ((unsigned)pos < (unsigned)N_EDGES)
        g_eidx[pos] = s;
}

// ---------------------------------------------------------------------------
// Fused conversion: W -> fp16 [m][k][n]; X -> g_A slot 0
// ---------------------------------------------------------------------------
#define W_G4 (5 * C_DIM * C_DIM / 4)          // 81920 float4-granules of W
#define X_G4 (N_NODES * C_DIM / 4)            // 3,200,000 granules of X
__global__ void conv_kernel(const float* __restrict__ relW,
                            const float* __restrict__ rootW,
                            const float* __restrict__ X) {
    int gid = blockIdx.x * blockDim.x + threadIdx.x;
    if (gid < W_G4) {
        const int i = gid * 4;        // element index into [5][64k]
        const int m = i >> 16;
        const int o = i & 65535;
        const float4 v = (m == 0)
            ? *reinterpret_cast<const float4*>(rootW + o)
            : *reinterpret_cast<const float4*>(relW + (size_t)(m - 1) * 65536 + o);
        __half h[4];
        h[0] = __float2half(v.x); h[1] = __float2half(v.y);
        h[2] = __float2half(v.z); h[3] = __float2half(v.w);
        *reinterpret_cast<uint2*>(g_W + i) = *reinterpret_cast<uint2*>(h);
    } else if (gid < W_G4 + X_G4) {
        const size_t i = (size_t)(gid - W_G4);
        const float4 v = reinterpret_cast<const float4*>(X)[i];
        __half h[4];
        h[0] = __float2half(v.x); h[1] = __float2half(v.y);
        h[2] = __float2half(v.z); h[3] = __float2half(v.w);
        *reinterpret_cast<uint2*>(g_A + 4 * i) = *reinterpret_cast<uint2*>(h);
    }
}

// ---------------------------------------------------------------------------
// Gather-mean per bucket over fp16 X -> g_A[1+r]  (edge loop unrolled x2)
// ---------------------------------------------------------------------------
__device__ __forceinline__ void acc_row(float* s, int src, int lane) {
    const uint4 raw = *reinterpret_cast<const uint4*>(
        g_A + (size_t)src * C_DIM + lane * 8);
    const __half2* hp = reinterpret_cast<const __half2*>(&raw);
    #pragma unroll
    for (int q = 0; q < 4; ++q) {
        const float2 f = __half22float2(hp[q]);
        s[2 * q]     += f.x;
        s[2 * q + 1] += f.y;
    }
}

__global__ void agg_kernel() {
    const int wid  = (blockIdx.x * blockDim.x + threadIdx.x) >> 5;
    const int lane = threadIdx.x & 31;
    if (wid >= NBUCKETS) return;

    const int deg   = g_deg[wid];
    const int start = g_off[wid] - deg;    // off was post-incremented by bucket

    float s[8] = {0.f, 0.f, 0.f, 0.f, 0.f, 0.f, 0.f, 0.f};
    float s2[8] = {0.f, 0.f, 0.f, 0.f, 0.f, 0.f, 0.f, 0.f};
    int e = 0;
    for (; e + 1 < deg; e += 2) {
        const int src0 = g_eidx[start + e];
        const int src1 = g_eidx[start + e + 1];
        acc_row(s,  src0, lane);
        acc_row(s2, src1, lane);
    }
    if (e < deg) acc_row(s, g_eidx[start + e], lane);
    #pragma unroll
    for (int q = 0; q < 8; ++q) s[q] += s2[q];

    const float inv = (deg > 0) ? (1.0f / (float)deg) : 0.0f;

    __half h[8];
    #pragma unroll
    for (int q = 0; q < 8; ++q) h[q] = __float2half(s[q] * inv);

    const size_t o = ((size_t)N_NODES * C_DIM) + (size_t)wid * C_DIM + lane * 8;
    *reinterpret_cast<uint4*>(g_A + o) = *reinterpret_cast<uint4*>(h);
}

// ---------------------------------------------------------------------------
// Dense GEMM (K=1280 concat, single-pass fp16) + gate epilogue.
// Tile M=128 x N=256, 512 threads = 16 warps (8m x 2n). 3-stage, KCH=64
// (the R11 pipeline: wait_group 1, prefetch distance 2).
// px (X . attW_x) computed in-kernel before the main loop.
// ---------------------------------------------------------------------------
#define MB      128
#define KCH     64
#define NCHUNK  20
#define SAW     72      // A smem row stride (half): 144B, conflict-free
#define SWW     264     // W smem row stride (half)
#define A_STAGE (MB * SAW)              // 9216 half
#define W_STAGE (KCH * SWW)             // 16896 half
#define STAGE_H (A_STAGE + W_STAGE)     // 26112 half
#define SMEM_BYTES (3 * STAGE_H * 2)    // 156,672 B

__device__ __forceinline__ void cp16(void* dst_smem, const void* src) {
    unsigned int d = (unsigned int)__cvta_generic_to_shared(dst_smem);
    asm volatile("cp.async.cg.shared.global [%0], [%1], 16;" :: "r"(d), "l"(src));
}
__device__ __forceinline__ void ldsm4(const void* p, unsigned& r0, unsigned& r1,
                                      unsigned& r2, unsigned& r3) {
    unsigned a = (unsigned)__cvta_generic_to_shared(p);
    asm volatile("ldmatrix.sync.aligned.m8n8.x4.shared.b16 {%0,%1,%2,%3}, [%4];"
                 : "=r"(r0), "=r"(r1), "=r"(r2), "=r"(r3) : "r"(a));
}
__device__ __forceinline__ void ldsm4t(const void* p, unsigned& r0, unsigned& r1,
                                       unsigned& r2, unsigned& r3) {
    unsigned a = (unsigned)__cvta_generic_to_shared(p);
    asm volatile("ldmatrix.sync.aligned.m8n8.x4.trans.shared.b16 {%0,%1,%2,%3}, [%4];"
                 : "=r"(r0), "=r"(r1), "=r"(r2), "=r"(r3) : "r"(a));
}
__device__ __forceinline__ void mma16816(float* c, unsigned a0, unsigned a1,
                                         unsigned a2, unsigned a3,
                                         unsigned b0, unsigned b1) {
    asm volatile(
        "mma.sync.aligned.m16n8k16.row.col.f32.f16.f16.f32 "
        "{%0,%1,%2,%3}, {%4,%5,%6,%7}, {%8,%9}, {%0,%1,%2,%3};"
        : "+f"(c[0]), "+f"(c[1]), "+f"(c[2]), "+f"(c[3])
        : "r"(a0), "r"(a1), "r"(a2), "r"(a3), "r"(b0), "r"(b1));
}

__global__ void __launch_bounds__(512, 1) gemm_gate(
    const float* __restrict__ X,
    const float* __restrict__ bias,
    const float* __restrict__ attW,
    const float* __restrict__ attB,
    float* __restrict__ out)
{
    extern __shared__ char smem_raw[];
    __half* sm = (__half*)smem_raw;
    float* pa = (float*)smem_raw;       // epilogue overlay
    __shared__ float spx[MB];           // px per tile row (static, survives overlay)

    const int t    = threadIdx.x;
    const int lane = t & 31;
    const int warp = t >> 5;
    const int wm   = warp & 7;      // 8 m-warps x 16 rows
    const int wn   = warp >> 3;     // 2 n-warps x 128 cols
    const int node0 = blockIdx.x * MB;

    float acc[16][4];
    #pragma unroll
    for (int i = 0; i < 16; ++i)
        #pragma unroll
        for (int j = 0; j < 4; ++j) acc[i][j] = 0.f;

    auto load_chunk = [&](int c, int stage) {
        const int m  = c >> 2;
        const int k0 = (c & 3) * KCH;
        __half* st = sm + stage * STAGE_H;
        // A: 128 rows x 8 segs = 1024 granules -> 2 per thread
        #pragma unroll
        for (int i = 0; i < 2; ++i) {
            const int p = t + 512 * i;          // 0..1023
            const int row = p >> 3, seg = p & 7;
            const int node = min(node0 + row, N_NODES - 1);
            const size_t g = ((size_t)m * N_NODES + node) * C_DIM + k0 + seg * 8;
            cp16(st + row * SAW + seg * 8, g_A + g);
        }
        // W: 64 rows x 32 segs = 2048 granules -> 4 per thread
        #pragma unroll
        for (int i = 0; i < 4; ++i) {
            const int p = t + 512 * i;          // 0..2047
            const int row = p >> 5, seg = p & 31;
            const size_t g = ((size_t)m * C_DIM + k0 + row) * C_DIM + seg * 8;
            cp16(st + A_STAGE + row * SWW + seg * 8, g_W + g);
        }
        asm volatile("cp.async.commit_group;");
    };

    load_chunk(0, 0);
    load_chunk(1, 1);

    // ---- px = X16[node] . attW[C:2C], 4 threads per row (overlaps loads) ----
    {
        const int prow = t >> 2;            // 0..127
        const int pq   = t & 3;
        const int pnode = min(node0 + prow, N_NODES - 1);
        const __half* xrow = g_A + (size_t)pnode * C_DIM + pq * 64;
        float pxv = 0.f;
        #pragma unroll
        for (int j = 0; j < 8; ++j) {
            const uint4 raw = *reinterpret_cast<const uint4*>(xrow + j * 8);
            const __half2* hp = reinterpret_cast<const __half2*>(&raw);
            #pragma unroll
            for (int q = 0; q < 4; ++q) {
                const float2 f = __half22float2(hp[q]);
                const int col = C_DIM + pq * 64 + j * 8 + 2 * q;
                pxv += f.x * attW[col] + f.y * attW[col + 1];
            }
        }
        pxv += __shfl_xor_sync(0xffffffffu, pxv, 1);
        pxv += __shfl_xor_sync(0xffffffffu, pxv, 2);
        if (pq == 0) spx[prow] = pxv;
    }

    for (int c = 0; c < NCHUNK; ++c) {
        if (c + 1 < NCHUNK) asm volatile("cp.async.wait_group 1;");
        else                asm volatile("cp.async.wait_group 0;");
        __syncthreads();   // stage c visible; stage (c-1)%3 consumers done

        if (c + 2 < NCHUNK) load_chunk(c + 2, (c + 2) % 3);

        const __half* st = sm + (c % 3) * STAGE_H;
        const __half* Wb = st + A_STAGE;

        #pragma unroll
        for (int s = 0; s < 4; ++s) {
            const __half* ap =
                st + (wm * 16 + (lane & 15)) * SAW + s * 16 + (lane >> 4) * 8;
            unsigned a0, a1, a2, a3;
            ldsm4(ap, a0, a1, a2, a3);

            const int krow = s * 16 + (lane & 15);
            #pragma unroll
            for (int nt2 = 0; nt2 < 8; ++nt2) {
                const int ncol = wn * 128 + nt2 * 16 + (lane >> 4) * 8;
                unsigned b0, b1, b2, b3;
                ldsm4t(Wb + krow * SWW + ncol, b0, b1, b2, b3);
                mma16816(acc[2 * nt2],     a0, a1, a2, a3, b0, b1);
                mma16816(acc[2 * nt2 + 1], a0, a1, a2, a3, b2, b3);
            }
        }
    }
    __syncthreads();   // all computes done before smem overlay

    // ---------------- epilogue (register-resident; px in spx) ----------
    const int r0   = lane >> 2;
    const int cq   = 2 * (lane & 3);
    const int row0 = wm * 16 + r0;
    const int n0g  = node0 + row0;
    const int n1g  = n0g + 8;
    const bool v0  = n0g < N_NODES;
    const bool v1  = n1g < N_NODES;

    float pz0 = 0.f, pz1 = 0.f;
    #pragma unroll
    for (int nt = 0; nt < 16; ++nt) {
        const int col = wn * 128 + (nt >> 1) * 16 + (nt & 1) * 8 + cq;
        const float b0 = bias[col], b1 = bias[col + 1];
        const float wu0 = attW[col], wu1 = attW[col + 1];
        pz0 += (acc[nt][0] + b0) * wu0 + (acc[nt][1] + b1) * wu1;
        pz1 += (acc[nt][2] + b0) * wu0 + (acc[nt][3] + b1) * wu1;
    }
    pz0 += __shfl_xor_sync(0xffffffffu, pz0, 1);
    pz0 += __shfl_xor_sync(0xffffffffu, pz0, 2);
    pz1 += __shfl_xor_sync(0xffffffffu, pz1, 1);
    pz1 += __shfl_xor_sync(0xffffffffu, pz1, 2);

    if ((lane & 3) == 0) {
        pa[row0 * 2 + wn]       = pz0;
        pa[(row0 + 8) * 2 + wn] = pz1;
    }
    __syncthreads();
    float* a_s = pa + 2 * MB;
    if (t < MB) {
        const float z = pa[t * 2] + pa[t * 2 + 1] + spx[t] + attB[0];
        a_s[t] = 1.0f / (1.0f + expf(-z));
    }
    __syncthreads();

    const float a0 = a_s[row0], a1 = a_s[row0 + 8];
    #pragma unroll
    for (int nt = 0; nt < 16; ++nt) {
        const int col = wn * 128 + (nt >> 1) * 16 + (nt & 1) * 8 + cq;
        const float b0 = bias[col], b1 = bias[col + 1];
        if (v0) {
            const float2 x2 = *reinterpret_cast<const float2*>(X + (size_t)n0g * C_DIM + col);
            float2 h;
            h.x = tanhf(acc[nt][0] + b0) * a0 + x2.x * (1.0f - a0);
            h.y = tanhf(acc[nt][1] + b1) * a0 + x2.y * (1.0f - a0);
            *reinterpret_cast<float2*>(out + (size_t)n0g * C_DIM + col) = h;
        }
        if (v1) {
            const float2 x2 = *reinterpret_cast<const float2*>(X + (size_t)n1g * C_DIM + col);
            float2 h;
            h.x = tanhf(acc[nt][2] + b0) * a1 + x2.x * (1.0f - a1);
            h.y = tanhf(acc[nt][3] + b1) * a1 + x2.y * (1.0f - a1);
            *reinterpret_cast<float2*>(out + (size_t)n1g * C_DIM + col) = h;
        }
    }
}

// ---------------------------------------------------------------------------
// Launch
// ---------------------------------------------------------------------------
extern "C" void kernel_launch(void* const* d_in, const int* in_sizes, int n_in,
                              void* d_out, int out_size) {
    const float* X     = (const float*)d_in[0];
    const int*   ei    = (const int*)d_in[1];     // int32
    const int*   et    = (const int*)d_in[2];     // int32
    const float* relW  = (const float*)d_in[3];
    const float* rootW = (const float*)d_in[4];
    const float* bias  = (const float*)d_in[5];
    const float* attW  = (const float*)d_in[6];
    const float* attB  = (const float*)d_in[7];
    float*       out   = (float*)d_out;
    (void)in_sizes; (void)n_in; (void)out_size;

    cudaFuncSetAttribute(gemm_gate,
                         cudaFuncAttributeMaxDynamicSharedMemorySize, SMEM_BYTES);

    zero_counts_kernel<<<(NBUCKETS + 255) / 256, 256>>>();
    hist_kernel<<<(N_EDGES + 255) / 256, 256>>>(ei, et);
    conv_kernel<<<(W_G4 + X_G4 + 255) / 256, 256>>>(relW, rootW, X);
    scan_blocks_kernel<<<NSCANBLK, SCAN_BS>>>();
    scan_top_kernel<<<1, 256>>>();
    scan_add_kernel<<<(NBUCKETS + 255) / 256, 256>>>();
    bucket_kernel<<<(N_EDGES + 255) / 256, 256>>>(ei, et);
    agg_kernel<<<(NBUCKETS * 32 + 255) / 256, 256>>>();
    gemm_gate<<<(N_NODES + MB - 1) / MB, 512, SMEM_BYTES>>>(X, bias, attW, attB, out);
}

// round 14
// speedup vs baseline: 1.0426x; 1.0374x over previous
#include <cuda_runtime.h>
#include <cuda_fp16.h>
#include <cstdint>
#include <cstddef>

#define N_NODES   50000
#define N_EDGES   800000
#define C_DIM     256
#define R_REL     4
#define NBUCKETS  (R_REL * N_NODES)
#define SCAN_BS   1024
#define NSCANBLK  ((NBUCKETS + SCAN_BS - 1) / SCAN_BS)

// -------------------- scratch --------------------
__device__ int g_deg[NBUCKETS];
__device__ int g_off[NBUCKETS];     // local (per-scan-block) exclusive prefix; bucket post-increments
__device__ int g_eidx[N_EDGES];
__device__ int g_bsum[SCAN_BS];
__device__ int g_bsumx[SCAN_BS];
__device__ float g_px[N_NODES];     // X[n] . attW[C:2C]  (fp32)
// fp16 weights [5][256][256] in [k][n] layout (root, rel0..3)
__device__ __half g_W[5 * C_DIM * C_DIM];
// fp16 A operand [5][N][256]: m=0 -> X(fp16), m=1..4 -> per-relation means
__device__ __half g_A[(size_t)5 * N_NODES * C_DIM];

__device__ __forceinline__ bool edge_ok(int s, int d, int r) {
    return ((unsigned)s < (unsigned)N_NODES) &&
           ((unsigned)d < (unsigned)N_NODES) &&
           ((unsigned)r < (unsigned)R_REL);
}

// ---------------------------------------------------------------------------
// Front kernel: zero g_deg | convert W -> fp16 | convert X -> fp16 + px dot
// Ranges are warp-aligned: NBUCKETS=200000 and W_G4=81920 both /32.
// ---------------------------------------------------------------------------
#define W_G4 (5 * C_DIM * C_DIM / 4)                  // 81920
#define FRONT_TOTAL (NBUCKETS + W_G4 + 32 * N_NODES)  // 1,881,920

__global__ void front_kernel(const float* __restrict__ relW,
                             const float* __restrict__ rootW,
                             const float* __restrict__ X,
                             const float* __restrict__ attW) {
    const int gid = blockIdx.x * blockDim.x + threadIdx.x;
    if (gid < NBUCKETS) {
        g_deg[gid] = 0;
    } else if (gid < NBUCKETS + W_G4) {
        const int i = (gid - NBUCKETS) * 4;   // element index into [5][64k]
        const int m = i >> 16;
        const int o = i & 65535;
        const float4 v = (m == 0)
            ? *reinterpret_cast<const float4*>(rootW + o)
            : *reinterpret_cast<const float4*>(relW + (size_t)(m - 1) * 65536 + o);
        __half h[4];
        h[0] = __float2half(v.x); h[1] = __float2half(v.y);
        h[2] = __float2half(v.z); h[3] = __float2half(v.w);
        *reinterpret_cast<uint2*>(g_W + i) = *reinterpret_cast<uint2*>(h);
    } else if (gid < FRONT_TOTAL) {
        // warp per X row: convert to fp16 + px dot
        const int xt   = gid - (NBUCKETS + W_G4);
        const int n    = xt >> 5;
        const int lane = xt & 31;
        const float4 v0 = *reinterpret_cast<const float4*>(X + (size_t)n * C_DIM + lane * 8);
        const float4 v1 = *reinterpret_cast<const float4*>(X + (size_t)n * C_DIM + lane * 8 + 4);
        __half h[8];
        h[0] = __float2half(v0.x); h[1] = __float2half(v0.y);
        h[2] = __float2half(v0.z); h[3] = __float2half(v0.w);
        h[4] = __float2half(v1.x); h[5] = __float2half(v1.y);
        h[6] = __float2half(v1.z); h[7] = __float2half(v1.w);
        *reinterpret_cast<uint4*>(g_A + (size_t)n * C_DIM + lane * 8) =
            *reinterpret_cast<uint4*>(h);

        const float* aw = attW + C_DIM + lane * 8;
        float s = v0.x * aw[0] + v0.y * aw[1] + v0.z * aw[2] + v0.w * aw[3]
                + v1.x * aw[4] + v1.y * aw[5] + v1.z * aw[6] + v1.w * aw[7];
        #pragma unroll
        for (int o = 16; o; o >>= 1) s += __shfl_xor_sync(0xffffffffu, s, o);
        if (lane == 0) g_px[n] = s;
    }
}

// ---------------------------------------------------------------------------
// CSR build (edges are INT32)
// ---------------------------------------------------------------------------
__global__ void hist_kernel(const int* __restrict__ edge_index,
                            const int* __restrict__ edge_type) {
    int e = blockIdx.x * blockDim.x + threadIdx.x;
    if (e >= N_EDGES) return;
    int s = edge_index[e];
    int d = edge_index[N_EDGES + e];
    int r = edge_type[e];
    if (!edge_ok(s, d, r)) return;
    atomicAdd(&g_deg[r * N_NODES + d], 1);
}

__global__ void scan_blocks_kernel() {
    __shared__ int sh[SCAN_BS];
    const int tid = threadIdx.x;
    const int gid = blockIdx.x * SCAN_BS + tid;
    int v = (gid < NBUCKETS) ? g_deg[gid] : 0;
    sh[tid] = v;
    __syncthreads();
    for (int o = 1; o < SCAN_BS; o <<= 1) {
        int t = (tid >= o) ? sh[tid - o] : 0;
        __syncthreads();
        sh[tid] += t;
        __syncthreads();
    }
    int incl = sh[tid];
    if (gid < NBUCKETS) g_off[gid] = incl - v;   // LOCAL exclusive prefix
    if (tid == SCAN_BS - 1) g_bsum[blockIdx.x] = incl;
}

__global__ void scan_top_kernel() {
    __shared__ int sh[256];
    const int tid = threadIdx.x;
    int v = (tid < NSCANBLK) ? g_bsum[tid] : 0;
    sh[tid] = v;
    __syncthreads();
    for (int o = 1; o < 256; o <<= 1) {
        int t = (tid >= o) ? sh[tid - o] : 0;
        __syncthreads();
        sh[tid] += t;
        __syncthreads();
    }
    g_bsumx[tid] = sh[tid] - v;   // exclusive block offsets
}

// bucket: pos = local-prefix post-increment + block offset (no scan_add pass)
__global__ void bucket_kernel(const int* __restrict__ edge_index,
                              const int* __restrict__ edge_type) {
    int e = blockIdx.x * blockDim.x + threadIdx.x;
    if (e >= N_EDGES) return;
    int s = edge_index[e];
    int d = edge_index[N_EDGES + e];
    int r = edge_type[e];
    if (!edge_ok(s, d, r)) return;
    int b = r * N_NODES + d;
    int pos = atomicAdd(&g_off[b], 1) + g_bsumx[b >> 10];
    if ((unsigned)pos < (unsigned)N_EDGES)
        g_eidx[pos] = s;
}

// ---------------------------------------------------------------------------
// Gather-mean per bucket over fp16 X -> g_A[1+r]  (edge loop unrolled x2)
// ---------------------------------------------------------------------------
__device__ __forceinline__ void acc_row(float* s, int src, int lane) {
    const uint4 raw = *reinterpret_cast<const uint4*>(
        g_A + (size_t)src * C_DIM + lane * 8);
    const __half2* hp = reinterpret_cast<const __half2*>(&raw);
    #pragma unroll
    for (int q = 0; q < 4; ++q) {
        const float2 f = __half22float2(hp[q]);
        s[2 * q]     += f.x;
        s[2 * q + 1] += f.y;
    }
}

__global__ void agg_kernel() {
    const int wid  = (blockIdx.x * blockDim.x + threadIdx.x) >> 5;
    const int lane = threadIdx.x & 31;
    if (wid >= NBUCKETS) return;

    const int deg   = g_deg[wid];
    // g_off[wid] is local-prefix + deg after bucket; add block offset for global
    const int start = g_off[wid] - deg + g_bsumx[wid >> 10];

    float s[8] = {0.f, 0.f, 0.f, 0.f, 0.f, 0.f, 0.f, 0.f};
    float s2[8] = {0.f, 0.f, 0.f, 0.f, 0.f, 0.f, 0.f, 0.f};
    int e = 0;
    for (; e + 1 < deg; e += 2) {
        const int src0 = g_eidx[start + e];
        const int src1 = g_eidx[start + e + 1];
        acc_row(s,  src0, lane);
        acc_row(s2, src1, lane);
    }
    if (e < deg) acc_row(s, g_eidx[start + e], lane);
    #pragma unroll
    for (int q = 0; q < 8; ++q) s[q] += s2[q];

    const float inv = (deg > 0) ? (1.0f / (float)deg) : 0.0f;

    __half h[8];
    #pragma unroll
    for (int q = 0; q < 8; ++q) h[q] = __float2half(s[q] * inv);

    const size_t o = ((size_t)N_NODES * C_DIM) + (size_t)wid * C_DIM + lane * 8;
    *reinterpret_cast<uint4*>(g_A + o) = *reinterpret_cast<uint4*>(h);
}

// ---------------------------------------------------------------------------
// Dense GEMM (K=1280 concat, single-pass fp16) + gate epilogue.
// EXACT R11 pipeline: M=128 x N=256, 512 threads, 3-stage, KCH=64, wait_group 1.
// px read from g_px in the epilogue.
// ---------------------------------------------------------------------------
#define MB      128
#define KCH     64
#define NCHUNK  20
#define SAW     72      // A smem row stride (half)
#define SWW     264     // W smem row stride (half)
#define A_STAGE (MB * SAW)              // 9216 half
#define W_STAGE (KCH * SWW)             // 16896 half
#define STAGE_H (A_STAGE + W_STAGE)     // 26112 half
#define SMEM_BYTES (3 * STAGE_H * 2)    // 156,672 B

__device__ __forceinline__ void cp16(void* dst_smem, const void* src) {
    unsigned int d = (unsigned int)__cvta_generic_to_shared(dst_smem);
    asm volatile("cp.async.cg.shared.global [%0], [%1], 16;" :: "r"(d), "l"(src));
}
__device__ __forceinline__ void ldsm4(const void* p, unsigned& r0, unsigned& r1,
                                      unsigned& r2, unsigned& r3) {
    unsigned a = (unsigned)__cvta_generic_to_shared(p);
    asm volatile("ldmatrix.sync.aligned.m8n8.x4.shared.b16 {%0,%1,%2,%3}, [%4];"
                 : "=r"(r0), "=r"(r1), "=r"(r2), "=r"(r3) : "r"(a));
}
__device__ __forceinline__ void ldsm4t(const void* p, unsigned& r0, unsigned& r1,
                                       unsigned& r2, unsigned& r3) {
    unsigned a = (unsigned)__cvta_generic_to_shared(p);
    asm volatile("ldmatrix.sync.aligned.m8n8.x4.trans.shared.b16 {%0,%1,%2,%3}, [%4];"
                 : "=r"(r0), "=r"(r1), "=r"(r2), "=r"(r3) : "r"(a));
}
__device__ __forceinline__ void mma16816(float* c, unsigned a0, unsigned a1,
                                         unsigned a2, unsigned a3,
                                         unsigned b0, unsigned b1) {
    asm volatile(
        "mma.sync.aligned.m16n8k16.row.col.f32.f16.f16.f32 "
        "{%0,%1,%2,%3}, {%4,%5,%6,%7}, {%8,%9}, {%0,%1,%2,%3};"
        : "+f"(c[0]), "+f"(c[1]), "+f"(c[2]), "+f"(c[3])
        : "r"(a0), "r"(a1), "r"(a2), "r"(a3), "r"(b0), "r"(b1));
}

__global__ void __launch_bounds__(512, 1) gemm_gate(
    const float* __restrict__ X,
    const float* __restrict__ bias,
    const float* __restrict__ attW,
    const float* __restrict__ attB,
    float* __restrict__ out)
{
    extern __shared__ char smem_raw[];
    __half* sm = (__half*)smem_raw;
    float* pa = (float*)smem_raw;       // epilogue overlay

    const int t    = threadIdx.x;
    const int lane = t & 31;
    const int warp = t >> 5;
    const int wm   = warp & 7;      // 8 m-warps x 16 rows
    const int wn   = warp >> 3;     // 2 n-warps x 128 cols
    const int node0 = blockIdx.x * MB;

    float acc[16][4];
    #pragma unroll
    for (int i = 0; i < 16; ++i)
        #pragma unroll
        for (int j = 0; j < 4; ++j) acc[i][j] = 0.f;

    auto load_chunk = [&](int c, int stage) {
        const int m  = c >> 2;
        const int k0 = (c & 3) * KCH;
        __half* st = sm + stage * STAGE_H;
        // A: 128 rows x 8 segs = 1024 granules -> 2 per thread
        #pragma unroll
        for (int i = 0; i < 2; ++i) {
            const int p = t + 512 * i;          // 0..1023
            const int row = p >> 3, seg = p & 7;
            const int node = min(node0 + row, N_NODES - 1);
            const size_t g = ((size_t)m * N_NODES + node) * C_DIM + k0 + seg * 8;
            cp16(st + row * SAW + seg * 8, g_A + g);
        }
        // W: 64 rows x 32 segs = 2048 granules -> 4 per thread
        #pragma unroll
        for (int i = 0; i < 4; ++i) {
            const int p = t + 512 * i;          // 0..2047
            const int row = p >> 5, seg = p & 31;
            const size_t g = ((size_t)m * C_DIM + k0 + row) * C_DIM + seg * 8;
            cp16(st + A_STAGE + row * SWW + seg * 8, g_W + g);
        }
        asm volatile("cp.async.commit_group;");
    };

    load_chunk(0, 0);
    load_chunk(1, 1);

    for (int c = 0; c < NCHUNK; ++c) {
        if (c + 1 < NCHUNK) asm volatile("cp.async.wait_group 1;");
        else                asm volatile("cp.async.wait_group 0;");
        __syncthreads();   // stage c visible; stage (c-1)%3 consumers done

        if (c + 2 < NCHUNK) load_chunk(c + 2, (c + 2) % 3);

        const __half* st = sm + (c % 3) * STAGE_H;
        const __half* Wb = st + A_STAGE;

        #pragma unroll
        for (int s = 0; s < 4; ++s) {
            const __half* ap =
                st + (wm * 16 + (lane & 15)) * SAW + s * 16 + (lane >> 4) * 8;
            unsigned a0, a1, a2, a3;
            ldsm4(ap, a0, a1, a2, a3);

            const int krow = s * 16 + (lane & 15);
            #pragma unroll
            for (int nt2 = 0; nt2 < 8; ++nt2) {
                const int ncol = wn * 128 + nt2 * 16 + (lane >> 4) * 8;
                unsigned b0, b1, b2, b3;
                ldsm4t(Wb + krow * SWW + ncol, b0, b1, b2, b3);
                mma16816(acc[2 * nt2],     a0, a1, a2, a3, b0, b1);
                mma16816(acc[2 * nt2 + 1], a0, a1, a2, a3, b2, b3);
            }
        }
    }
    __syncthreads();   // all computes done before smem overlay

    // ---------------- epilogue (register-resident; px precomputed) ----------
    const int r0   = lane >> 2;
    const int cq   = 2 * (lane & 3);
    const int row0 = wm * 16 + r0;
    const int n0g  = node0 + row0;
    const int n1g  = n0g + 8;
    const bool v0  = n0g < N_NODES;
    const bool v1  = n1g < N_NODES;

    float pz0 = 0.f, pz1 = 0.f;
    #pragma unroll
    for (int nt = 0; nt < 16; ++nt) {
        const int col = wn * 128 + (nt >> 1) * 16 + (nt & 1) * 8 + cq;
        const float b0 = bias[col], b1 = bias[col + 1];
        const float wu0 = attW[col], wu1 = attW[col + 1];
        pz0 += (acc[nt][0] + b0) * wu0 + (acc[nt][1] + b1) * wu1;
        pz1 += (acc[nt][2] + b0) * wu0 + (acc[nt][3] + b1) * wu1;
    }
    pz0 += __shfl_xor_sync(0xffffffffu, pz0, 1);
    pz0 += __shfl_xor_sync(0xffffffffu, pz0, 2);
    pz1 += __shfl_xor_sync(0xffffffffu, pz1, 1);
    pz1 += __shfl_xor_sync(0xffffffffu, pz1, 2);

    if ((lane & 3) == 0) {
        pa[row0 * 2 + wn]       = pz0;
        pa[(row0 + 8) * 2 + wn] = pz1;
    }
    __syncthreads();
    float* a_s = pa + 2 * MB;
    if (t < MB) {
        const int node = node0 + t;
        const float px = (node < N_NODES) ? g_px[node] : 0.f;
        const float z = pa[t * 2] + pa[t * 2 + 1] + px + attB[0];
        a_s[t] = 1.0f / (1.0f + expf(-z));
    }
    __syncthreads();

    const float a0 = a_s[row0], a1 = a_s[row0 + 8];
    #pragma unroll
    for (int nt = 0; nt < 16; ++nt) {
        const int col = wn * 128 + (nt >> 1) * 16 + (nt & 1) * 8 + cq;
        const float b0 = bias[col], b1 = bias[col + 1];
        if (v0) {
            const float2 x2 = *reinterpret_cast<const float2*>(X + (size_t)n0g * C_DIM + col);
            float2 h;
            h.x = tanhf(acc[nt][0] + b0) * a0 + x2.x * (1.0f - a0);
            h.y = tanhf(acc[nt][1] + b1) * a0 + x2.y * (1.0f - a0);
            *reinterpret_cast<float2*>(out + (size_t)n0g * C_DIM + col) = h;
        }
        if (v1) {
            const float2 x2 = *reinterpret_cast<const float2*>(X + (size_t)n1g * C_DIM + col);
            float2 h;
            h.x = tanhf(acc[nt][2] + b0) * a1 + x2.x * (1.0f - a1);
            h.y = tanhf(acc[nt][3] + b1) * a1 + x2.y * (1.0f - a1);
            *reinterpret_cast<float2*>(out + (size_t)n1g * C_DIM + col) = h;
        }
    }
}

// ---------------------------------------------------------------------------
// Launch
// ---------------------------------------------------------------------------
extern "C" void kernel_launch(void* const* d_in, const int* in_sizes, int n_in,
                              void* d_out, int out_size) {
    const float* X     = (const float*)d_in[0];
    const int*   ei    = (const int*)d_in[1];     // int32
    const int*   et    = (const int*)d_in[2];     // int32
    const float* relW  = (const float*)d_in[3];
    const float* rootW = (const float*)d_in[4];
    const float* bias  = (const float*)d_in[5];
    const float* attW  = (const float*)d_in[6];
    const float* attB  = (const float*)d_in[7];
    float*       out   = (float*)d_out;
    (void)in_sizes; (void)n_in; (void)out_size;

    cudaFuncSetAttribute(gemm_gate,
                         cudaFuncAttributeMaxDynamicSharedMemorySize, SMEM_BYTES);

    front_kernel<<<(FRONT_TOTAL + 255) / 256, 256>>>(relW, rootW, X, attW);
    hist_kernel<<<(N_EDGES + 255) / 256, 256>>>(ei, et);
    scan_blocks_kernel<<<NSCANBLK, SCAN_BS>>>();
    scan_top_kernel<<<1, 256>>>();
    bucket_kernel<<<(N_EDGES + 255) / 256, 256>>>(ei, et);
    agg_kernel<<<(NBUCKETS * 32 + 255) / 256, 256>>>();
    gemm_gate<<<(N_NODES + MB - 1) / MB, 512, SMEM_BYTES>>>(X, bias, attW, attB, out);
}